// round 13
// baseline (speedup 1.0000x reference)
#include <cuda_runtime.h>
#include <cstdint>

#define V_N 65536
#define E_N 4096
#define P_N 4096
#define T_N 512
#define SENTF 1000000000.0f
#define BIGF  1e30f
#define INFF  __int_as_float(0x7f800000)

#define PT_BLOCKS 2048          // 2048 blocks * 2 warps = 4096 points

// Scratch (device globals: no allocations allowed)
__device__ float2 g_passA[E_N];   // (xmn, xmx)
__device__ float4 g_passB[E_N];   // (ymn, ymx, -b*w, w)   w = 1/a
__device__ float2 g_ab[E_N];      // (a, b)
__device__ float4 g_tbl[T_N];     // TableR cols 3..6
__device__ float  g_m[P_N];
__device__ int    g_valid[P_N];
__device__ int    g_done = 0;     // last-block counter (reset by last block)

// Predicated pass-2 update (verified body, non-volatile so ptxas can schedule)
#define PASS2_BODY(q)                                                      \
    {                                                                      \
        float xi = fmaf(cy, (q).w, (q).z);                                 \
        asm("{\n\t"                                                        \
            ".reg .pred pc, pg, pl;\n\t"                                   \
            "setp.gt.f32 pc, %6, %7;\n\t"                                  \
            "setp.lt.and.f32 pc, %6, %8, pc;\n\t"                          \
            "@pc add.s32 %4, %4, 1;\n\t"                                   \
            "@pc max.f32 %0, %0, %5;\n\t"                                  \
            "@pc min.f32 %1, %1, %5;\n\t"                                  \
            "setp.ge.and.f32 pg, %5, %9, pc;\n\t"                          \
            "setp.lt.and.f32 pl, %5, %9, pc;\n\t"                          \
            "@pg min.f32 %2, %2, %5;\n\t"                                  \
            "@pl max.f32 %3, %3, %5;\n\t"                                  \
            "}"                                                            \
            : "+f"(xallmx), "+f"(xallmn), "+f"(xs), "+f"(xinf), "+r"(n)    \
            : "f"(xi), "f"(cy), "f"((q).x), "f"((q).y), "f"(px));          \
    }

#define TBL_BODY(r)                                                        \
    {                                                                      \
        float al = fabsf(L1v - (r).x) + fabsf(L2v - (r).y)                 \
                 + fabsf(d1  - (r).z) + fabsf(d2  - (r).w);                \
        pm = fminf(pm, al);                                                \
    }

// ---------------------------------------------------------------------------
// K1: per-edge precompute + table extraction
// ---------------------------------------------------------------------------
__global__ void __launch_bounds__(64) prep_kernel(
        const float* __restrict__ verts,
        const float* __restrict__ tableR,
        const int*   __restrict__ edges) {
    int e = blockIdx.x * blockDim.x + threadIdx.x;
    if (e < T_N) {
        const float* r = tableR + e * 7;
        g_tbl[e] = make_float4(r[3], r[4], r[5], r[6]);
    }
    if (e < E_N) {
        int i0 = edges[2 * e + 0];
        int i1 = edges[2 * e + 1];
        float x0 = verts[3 * i0 + 0], y0 = verts[3 * i0 + 1];
        float x1 = verts[3 * i1 + 0], y1 = verts[3 * i1 + 1];
        float a = (y0 - y1) / (x0 - x1);                 // IEEE div (matches ref)
        float b = __fsub_rn(y0, __fmul_rn(a, x0));       // no FMA contraction
        float w = 1.0f / a;
        float nbw = -__fmul_rn(b, w);                    // xi = fma(cy, w, nbw)
        g_passA[e] = make_float2(fminf(x0, x1), fmaxf(x0, x1));
        g_passB[e] = make_float4(fminf(y0, y1), fmaxf(y0, y1), nbw, w);
        g_ab[e]    = make_float2(a, b);
    }
}

// ---------------------------------------------------------------------------
// K2: warp-per-point, 64-thread blocks (fine-grain balancing), 4-wide batch,
//     fused last-block scan.  2048 blocks * 2 warps = 4096 points.
// ---------------------------------------------------------------------------
__global__ void __launch_bounds__(64, 12) point_kernel(
        const float* __restrict__ verts,
        const int*   __restrict__ listAll,
        float*       __restrict__ out) {
    const unsigned FULL = 0xffffffffu;
    const int tid  = threadIdx.x;
    const int lane = tid & 31;
    const int warp = tid >> 5;               // 0..1
    const int p = blockIdx.x * 2 + warp;

    int li = __ldg(&listAll[p]);
    float px = __ldg(&verts[3 * li + 0]);
    float py = __ldg(&verts[3 * li + 1]);

    // ---- Pass 1: first edge with px strictly inside (xmn, xmx) ----
    int idx = 0x7fffffff;
    for (int e = lane; e < E_N; e += 32) {
        float2 mm = __ldg(&g_passA[e]);
        if (px > mm.x && px < mm.y) { idx = e; break; }   // lane stream ascending
    }
    #pragma unroll
    for (int o = 16; o; o >>= 1)
        idx = min(idx, __shfl_xor_sync(FULL, idx, o));
    if (idx == 0x7fffffff) idx = E_N - 1;

    float2 ab = __ldg(&g_ab[idx]);
    float exposeY = __fadd_rn(__fmul_rn(ab.x, px), ab.y);  // no FMA contraction
    float L1v = fabsf(py - exposeY);
    float cy  = (py + exposeY) * 0.5f;

    // ---- Pass 2: 32 outer iterations, 4 LDG.128 in flight each ----
    int n = 0;
    float xallmx = -SENTF, xallmn = SENTF;
    float xs = SENTF, xinf = -SENTF;
    {
        const float4* __restrict__ pB = g_passB + lane;
        #pragma unroll 1
        for (int k = 0; k < E_N / 128; k++) {
            float4 q0 = __ldg(pB +  0);
            float4 q1 = __ldg(pB + 32);
            float4 q2 = __ldg(pB + 64);
            float4 q3 = __ldg(pB + 96);
            pB += 128;
            PASS2_BODY(q0);
            PASS2_BODY(q1);
            PASS2_BODY(q2);
            PASS2_BODY(q3);
        }
    }
    #pragma unroll
    for (int o = 16; o; o >>= 1) {
        n      +=              __shfl_xor_sync(FULL, n,      o);
        xallmx = fmaxf(xallmx, __shfl_xor_sync(FULL, xallmx, o));
        xallmn = fminf(xallmn, __shfl_xor_sync(FULL, xallmn, o));
        xs     = fminf(xs,     __shfl_xor_sync(FULL, xs,     o));
        xinf   = fmaxf(xinf,   __shfl_xor_sync(FULL, xinf,   o));
    }

    // condB => xi in [0,1]; presence <=> sentinel moved
    int hs = xs   <  SENTF;
    int hi = xinf > -SENTF;
    int valid = (n == 2) || (n > 2 && hs && hi);
    float dx  = (n == 2) ? (xallmx - xallmn) : (xs - xinf);
    float L2v = fabsf(dx);
    float d1  = fabsf(cy - 1.0f);
    float d2  = fabsf(px - 1.0f);

    // ---- Table min: 4 outer iterations, 4 loads in flight ----
    float pm = INFF;
    {
        const float4* __restrict__ pT = g_tbl + lane;
        #pragma unroll 1
        for (int k = 0; k < T_N / 128; k++) {
            float4 r0 = __ldg(pT +  0);
            float4 r1 = __ldg(pT + 32);
            float4 r2 = __ldg(pT + 64);
            float4 r3 = __ldg(pT + 96);
            pT += 128;
            TBL_BODY(r0); TBL_BODY(r1); TBL_BODY(r2); TBL_BODY(r3);
        }
    }
    #pragma unroll
    for (int o = 16; o; o >>= 1)
        pm = fminf(pm, __shfl_xor_sync(FULL, pm, o));

    if (lane == 0) {
        g_m[p]     = valid ? pm : BIGF;
        g_valid[p] = valid;
    }

    // ================== fused scan: last-finishing block ==================
    __shared__ int s_last;
    __threadfence();
    __syncthreads();
    if (tid == 0) {
        int old = atomicAdd(&g_done, 1);
        s_last = (old == (int)gridDim.x - 1);
    }
    __syncthreads();
    if (!s_last) return;

    {   // 64 threads, 64 values each; two-pass so no 64-reg array
        __shared__ float s_wtot[2];
        __shared__ float s_sum[2];
        const int base = tid * 64;

        // pass A: chunk min
        float tot = INFF;
        #pragma unroll 4
        for (int i = 0; i < 64; i++)
            tot = fminf(tot, g_m[base + i]);

        // warp inclusive min-scan of chunk minima
        float scan = tot;
        #pragma unroll
        for (int o = 1; o < 32; o <<= 1) {
            float v = __shfl_up_sync(FULL, scan, o);
            if (lane >= o) scan = fminf(scan, v);
        }
        if (lane == 31) s_wtot[warp] = scan;
        __syncthreads();

        float wpre = (warp == 1) ? s_wtot[0] : INFF;
        float lpre = __shfl_up_sync(FULL, scan, 1);
        float pre = fminf(wpre, (lane == 0) ? INFF : lpre);

        // pass B: running cummin + masked sum
        float acc = 0.0f;
        float run = INFF;
        #pragma unroll 4
        for (int i = 0; i < 64; i++) {
            run = fminf(run, g_m[base + i]);
            if (g_valid[base + i]) acc += fminf(pre, run);
        }

        #pragma unroll
        for (int o = 16; o; o >>= 1)
            acc += __shfl_xor_sync(FULL, acc, o);
        if (lane == 0) s_sum[warp] = acc;
        __syncthreads();
        if (tid == 0) {
            out[0] = s_sum[0] + s_sum[1];
            g_done = 0;                   // reset for next graph replay
        }
    }
}

// ---------------------------------------------------------------------------
extern "C" void kernel_launch(void* const* d_in, const int* in_sizes, int n_in,
                              void* d_out, int out_size) {
    const float* verts   = (const float*)d_in[0];
    const float* tableR  = (const float*)d_in[1];
    const int*   edges   = (const int*)  d_in[2];
    const int*   listAll = (const int*)  d_in[3];

    prep_kernel <<<64,        64>>>(verts, tableR, edges);
    point_kernel<<<PT_BLOCKS, 64>>>(verts, listAll, (float*)d_out);
}

// round 14
// speedup vs baseline: 1.1352x; 1.1352x over previous
#include <cuda_runtime.h>
#include <cstdint>

#define V_N 65536
#define E_N 4096
#define P_N 4096
#define T_N 512
#define K_BINS 4
#define CAP (E_N * K_BINS)       // worst case: every edge in every bin
#define SENTF 1000000000.0f
#define BIGF  1e30f
#define INFF  __int_as_float(0x7f800000)

// Scratch (device globals: no allocations allowed)
__device__ float2 g_passA[E_N];     // (xmn, xmx)
__device__ float4 g_passB[E_N];     // (ymn, ymx, -b*w, w)   w = 1/a
__device__ float2 g_ab[E_N];        // (a, b)
__device__ float4 g_tbl[T_N];       // TableR cols 3..6
__device__ float4 g_binned[CAP];    // per-bin candidate lists (avg ~153 KB used)
__device__ int    g_binoff[K_BINS + 1];
__device__ float  g_m[P_N];
__device__ int    g_valid[P_N];

__device__ __forceinline__ int bin_of(float y) {
    int b = (int)floorf(y * (float)K_BINS);
    return min(K_BINS - 1, max(0, b));
}

// Predicated pass-2 update (R9's verified body)
#define PASS2_BODY(q)                                                      \
    {                                                                      \
        float xi = fmaf(cy, (q).w, (q).z);                                 \
        asm("{\n\t"                                                        \
            ".reg .pred pc, pg, pl;\n\t"                                   \
            "setp.gt.f32 pc, %6, %7;\n\t"                                  \
            "setp.lt.and.f32 pc, %6, %8, pc;\n\t"                          \
            "@pc add.s32 %4, %4, 1;\n\t"                                   \
            "@pc max.f32 %0, %0, %5;\n\t"                                  \
            "@pc min.f32 %1, %1, %5;\n\t"                                  \
            "setp.ge.and.f32 pg, %5, %9, pc;\n\t"                          \
            "setp.lt.and.f32 pl, %5, %9, pc;\n\t"                          \
            "@pg min.f32 %2, %2, %5;\n\t"                                  \
            "@pl max.f32 %3, %3, %5;\n\t"                                  \
            "}"                                                            \
            : "+f"(xallmx), "+f"(xallmn), "+f"(xs), "+f"(xinf), "+r"(n)    \
            : "f"(xi), "f"(cy), "f"((q).x), "f"((q).y), "f"(px));          \
    }

// ---------------------------------------------------------------------------
// K1: per-edge precompute + table extraction
// ---------------------------------------------------------------------------
__global__ void __launch_bounds__(64) prep_kernel(
        const float* __restrict__ verts,
        const float* __restrict__ tableR,
        const int*   __restrict__ edges) {
    int e = blockIdx.x * blockDim.x + threadIdx.x;
    if (e < T_N) {
        const float* r = tableR + e * 7;
        g_tbl[e] = make_float4(r[3], r[4], r[5], r[6]);
    }
    if (e < E_N) {
        int i0 = edges[2 * e + 0];
        int i1 = edges[2 * e + 1];
        float x0 = verts[3 * i0 + 0], y0 = verts[3 * i0 + 1];
        float x1 = verts[3 * i1 + 0], y1 = verts[3 * i1 + 1];
        float a = (y0 - y1) / (x0 - x1);                 // IEEE div (matches ref)
        float b = __fsub_rn(y0, __fmul_rn(a, x0));       // no FMA contraction
        float w = 1.0f / a;
        float nbw = -__fmul_rn(b, w);                    // xi = fma(cy, w, nbw)
        g_passA[e] = make_float2(fminf(x0, x1), fmaxf(x0, x1));
        g_passB[e] = make_float4(fminf(y0, y1), fmaxf(y0, y1), nbw, w);
        g_ab[e]    = make_float2(a, b);
    }
}

// ---------------------------------------------------------------------------
// K2: bin build — ONE block, all state launch-local (replay-deterministic)
// ---------------------------------------------------------------------------
__global__ void __launch_bounds__(1024) build_kernel() {
    const unsigned FULL = 0xffffffffu;
    __shared__ int s_cnt[K_BINS];
    __shared__ int s_off[K_BINS + 1];
    __shared__ int s_cur[K_BINS];
    const int tid  = threadIdx.x;
    const int lane = tid & 31;

    if (tid < K_BINS) s_cnt[tid] = 0;
    __syncthreads();

    // ---- pass 1: counts via warp-ballot aggregation ----
    #pragma unroll
    for (int j = 0; j < E_N / 1024; j++) {
        int e = tid + j * 1024;
        float4 q = g_passB[e];
        int b0 = bin_of(q.x), b1 = bin_of(q.y);
        #pragma unroll
        for (int bb = 0; bb < K_BINS; bb++) {
            unsigned m = __ballot_sync(FULL, b0 <= bb && bb <= b1);
            if (lane == 0 && m) atomicAdd(&s_cnt[bb], __popc(m));
        }
    }
    __syncthreads();

    if (tid == 0) {
        int acc = 0;
        #pragma unroll
        for (int bb = 0; bb < K_BINS; bb++) { s_off[bb] = acc; s_cur[bb] = acc; acc += s_cnt[bb]; }
        s_off[K_BINS] = acc;
    }
    __syncthreads();

    // ---- pass 2: scatter (order within a bin is irrelevant: commutative) ----
    #pragma unroll
    for (int j = 0; j < E_N / 1024; j++) {
        int e = tid + j * 1024;
        float4 q = g_passB[e];
        int b0 = bin_of(q.x), b1 = bin_of(q.y);
        #pragma unroll
        for (int bb = 0; bb < K_BINS; bb++) {
            bool cov = (b0 <= bb && bb <= b1);
            unsigned m = __ballot_sync(FULL, cov);
            if (m) {
                int base = 0;
                if (lane == 0) base = atomicAdd(&s_cur[bb], __popc(m));
                base = __shfl_sync(FULL, base, 0);
                if (cov) {
                    int slot = base + __popc(m & ((1u << lane) - 1u));
                    g_binned[slot] = q;
                }
            }
        }
    }
    __syncthreads();
    if (tid <= K_BINS) g_binoff[tid] = s_off[tid];
}

// ---------------------------------------------------------------------------
// K3: warp-per-point (R9 topology+body), pass-2 over bin(cy) candidates only
// ---------------------------------------------------------------------------
__global__ void __launch_bounds__(256, 3) point_kernel(
        const float* __restrict__ verts,
        const int*   __restrict__ listAll) {
    const unsigned FULL = 0xffffffffu;
    const int lane = threadIdx.x & 31;
    const int warp = threadIdx.x >> 5;
    const int p = blockIdx.x * 8 + warp;     // 512 blocks * 8 warps

    int li = __ldg(&listAll[p]);
    float px = __ldg(&verts[3 * li + 0]);
    float py = __ldg(&verts[3 * li + 1]);

    // ---- Pass 1: first edge with px strictly inside (xmn, xmx) ----
    int idx = 0x7fffffff;
    for (int e = lane; e < E_N; e += 32) {
        float2 mm = __ldg(&g_passA[e]);
        if (px > mm.x && px < mm.y) { idx = e; break; }   // lane stream ascending
    }
    #pragma unroll
    for (int o = 16; o; o >>= 1)
        idx = min(idx, __shfl_xor_sync(FULL, idx, o));
    if (idx == 0x7fffffff) idx = E_N - 1;

    float2 ab = __ldg(&g_ab[idx]);
    float exposeY = __fadd_rn(__fmul_rn(ab.x, px), ab.y);  // no FMA contraction
    float L1v = fabsf(py - exposeY);
    float cy  = (py + exposeY) * 0.5f;

    // ---- Pass 2: only this cy-bin's candidates (exact condB re-check) ----
    int bin = bin_of(cy);                    // warp-uniform
    int beg = __ldg(&g_binoff[bin]);
    int end = __ldg(&g_binoff[bin + 1]);

    int n = 0;
    float xallmx = -SENTF, xallmn = SENTF;
    float xs = SENTF, xinf = -SENTF;
    #pragma unroll 4
    for (int e = beg + lane; e < end; e += 32) {
        float4 q = __ldg(&g_binned[e]);      // (ymn, ymx, nbw, w)
        PASS2_BODY(q);
    }
    #pragma unroll
    for (int o = 16; o; o >>= 1) {
        n      +=              __shfl_xor_sync(FULL, n,      o);
        xallmx = fmaxf(xallmx, __shfl_xor_sync(FULL, xallmx, o));
        xallmn = fminf(xallmn, __shfl_xor_sync(FULL, xallmn, o));
        xs     = fminf(xs,     __shfl_xor_sync(FULL, xs,     o));
        xinf   = fmaxf(xinf,   __shfl_xor_sync(FULL, xinf,   o));
    }

    // condB => xi in [0,1]; presence <=> sentinel moved
    int hs = xs   <  SENTF;
    int hi = xinf > -SENTF;
    int valid = (n == 2) || (n > 2 && hs && hi);
    float dx  = (n == 2) ? (xallmx - xallmn) : (xs - xinf);
    float L2v = fabsf(dx);
    float d1  = fabsf(cy - 1.0f);
    float d2  = fabsf(px - 1.0f);

    // ---- Table min over T=512 rows ----
    float pm = INFF;
    #pragma unroll 4
    for (int t = lane; t < T_N; t += 32) {
        float4 r = __ldg(&g_tbl[t]);
        float al = fabsf(L1v - r.x) + fabsf(L2v - r.y)
                 + fabsf(d1  - r.z) + fabsf(d2  - r.w);
        pm = fminf(pm, al);
    }
    #pragma unroll
    for (int o = 16; o; o >>= 1)
        pm = fminf(pm, __shfl_xor_sync(FULL, pm, o));

    if (lane == 0) {
        g_m[p]     = valid ? pm : BIGF;
        g_valid[p] = valid;
    }
}

// ---------------------------------------------------------------------------
// K4: cummin + masked sum (1 block, 256 threads) — R9's verified scan
// ---------------------------------------------------------------------------
__global__ void __launch_bounds__(256) scan_kernel(float* __restrict__ out) {
    const unsigned FULL = 0xffffffffu;
    __shared__ float s_wtot[8];
    __shared__ float s_sum[8];
    const int tid  = threadIdx.x;
    const int lane = tid & 31;
    const int wid  = tid >> 5;
    const int base = tid * 16;

    float c[16];
    float run = INFF;
    #pragma unroll
    for (int i = 0; i < 16; i++) {
        run = fminf(run, g_m[base + i]);
        c[i] = run;
    }

    float scan = run;
    #pragma unroll
    for (int o = 1; o < 32; o <<= 1) {
        float v = __shfl_up_sync(FULL, scan, o);
        if (lane >= o) scan = fminf(scan, v);
    }
    if (lane == 31) s_wtot[wid] = scan;
    __syncthreads();

    float wpre = INFF;
    #pragma unroll
    for (int w = 0; w < 8; w++)
        if (w < wid) wpre = fminf(wpre, s_wtot[w]);

    float lpre = __shfl_up_sync(FULL, scan, 1);
    float pre = fminf(wpre, (lane == 0) ? INFF : lpre);

    float acc = 0.0f;
    #pragma unroll
    for (int i = 0; i < 16; i++)
        if (g_valid[base + i]) acc += fminf(pre, c[i]);

    #pragma unroll
    for (int o = 16; o; o >>= 1)
        acc += __shfl_xor_sync(FULL, acc, o);
    if (lane == 0) s_sum[wid] = acc;
    __syncthreads();
    if (tid == 0) {
        float s = 0.0f;
        #pragma unroll
        for (int w = 0; w < 8; w++) s += s_sum[w];
        out[0] = s;
    }
}

// ---------------------------------------------------------------------------
extern "C" void kernel_launch(void* const* d_in, const int* in_sizes, int n_in,
                              void* d_out, int out_size) {
    const float* verts   = (const float*)d_in[0];
    const float* tableR  = (const float*)d_in[1];
    const int*   edges   = (const int*)  d_in[2];
    const int*   listAll = (const int*)  d_in[3];

    prep_kernel <<<64,   64>>>(verts, tableR, edges);
    build_kernel<<<1,  1024>>>();
    point_kernel<<<512, 256>>>(verts, listAll);
    scan_kernel <<<1,   256>>>((float*)d_out);
}

// round 17
// speedup vs baseline: 2.1074x; 1.8565x over previous
#include <cuda_runtime.h>
#include <cstdint>

#define V_N 65536
#define E_N 4096
#define P_N 4096
#define T_N 512
#define SENTF 1000000000.0f
#define BIGF  1e30f
#define INFF  __int_as_float(0x7f800000)

// Scratch (device globals: no allocations allowed)
__device__ float2 g_passA[E_N];   // (xmn, xmx)
__device__ float4 g_passB[E_N];   // (ymn, ymx, -b*w, w)   w = 1/a
__device__ float2 g_ab[E_N];      // (a, b)
__device__ float4 g_tbl[T_N];     // TableR cols 3..6
__device__ float  g_m[P_N];
__device__ int    g_valid[P_N];

// ---------------------------------------------------------------------------
// K1: per-edge precompute + table extraction
// ---------------------------------------------------------------------------
__global__ void __launch_bounds__(64) prep_kernel(
        const float* __restrict__ verts,
        const float* __restrict__ tableR,
        const int*   __restrict__ edges) {
    int e = blockIdx.x * blockDim.x + threadIdx.x;
    if (e < T_N) {
        const float* r = tableR + e * 7;
        g_tbl[e] = make_float4(r[3], r[4], r[5], r[6]);
    }
    if (e < E_N) {
        int i0 = edges[2 * e + 0];
        int i1 = edges[2 * e + 1];
        float x0 = verts[3 * i0 + 0], y0 = verts[3 * i0 + 1];
        float x1 = verts[3 * i1 + 0], y1 = verts[3 * i1 + 1];
        float a = (y0 - y1) / (x0 - x1);                 // IEEE div (matches ref)
        float b = __fsub_rn(y0, __fmul_rn(a, x0));       // no FMA contraction
        float w = 1.0f / a;
        float nbw = -__fmul_rn(b, w);                    // xi = fma(cy, w, nbw)
        g_passA[e] = make_float2(fminf(x0, x1), fmaxf(x0, x1));
        g_passB[e] = make_float4(fminf(y0, y1), fmaxf(y0, y1), nbw, w);
        g_ab[e]    = make_float2(a, b);
    }
}

// ---------------------------------------------------------------------------
// K2: warp-per-point (R9 best-measured) with ballot-based pass-1
//     Block = 256 threads = 8 warps = 8 points. 512 blocks.
// ---------------------------------------------------------------------------
__global__ void __launch_bounds__(256) point_kernel(
        const float* __restrict__ verts,
        const int*   __restrict__ listAll) {
    const unsigned FULL = 0xffffffffu;
    const int lane = threadIdx.x & 31;
    const int warp = threadIdx.x >> 5;
    const int p = blockIdx.x * 8 + warp;     // 512 blocks * 8 warps

    int li = __ldg(&listAll[p]);
    float px = __ldg(&verts[3 * li + 0]);
    float py = __ldg(&verts[3 * li + 1]);

    // ---- Pass 1: first edge with px strictly inside (xmn, xmx) ----
    // Ballot chunk scan: warp-uniform exit at the FIRST 32-edge chunk with a
    // hit; lowest set lane there = global first index (exact argmax semantics).
    int idx = E_N - 1;                        // jnp.where(!any, E-1, argmax)
    for (int eb = 0; eb < E_N; eb += 32) {
        float2 mm = __ldg(&g_passA[eb + lane]);
        unsigned m = __ballot_sync(FULL, px > mm.x && px < mm.y);
        if (m) { idx = eb + __ffs(m) - 1; break; }
    }

    float2 ab = __ldg(&g_ab[idx]);
    float exposeY = __fadd_rn(__fmul_rn(ab.x, px), ab.y);  // no FMA contraction
    float L1v = fabsf(py - exposeY);
    float cy  = (py + exposeY) * 0.5f;

    // ---- Pass 2: predicated updates, straight from L1 ----
    int n = 0;
    float xallmx = -SENTF, xallmn = SENTF;
    float xs = SENTF, xinf = -SENTF;
    #pragma unroll 8
    for (int e = lane; e < E_N; e += 32) {
        float4 q = __ldg(&g_passB[e]);        // (ymn, ymx, nbw, w)
        float xi = fmaf(cy, q.w, q.z);        // (cy-b)*w  (<=2 ulp vs ref)
        asm volatile(
            "{\n\t"
            ".reg .pred pc, pg, pl;\n\t"
            "setp.gt.f32 pc, %6, %7;\n\t"          // cy > ymn
            "setp.lt.and.f32 pc, %6, %8, pc;\n\t"  // && cy < ymx
            "@pc add.s32 %4, %4, 1;\n\t"
            "@pc max.f32 %0, %0, %5;\n\t"
            "@pc min.f32 %1, %1, %5;\n\t"
            "setp.ge.and.f32 pg, %5, %9, pc;\n\t"  // condB && xi >= px
            "setp.lt.and.f32 pl, %5, %9, pc;\n\t"  // condB && xi <  px
            "@pg min.f32 %2, %2, %5;\n\t"
            "@pl max.f32 %3, %3, %5;\n\t"
            "}"
            : "+f"(xallmx), "+f"(xallmn), "+f"(xs), "+f"(xinf), "+r"(n)
            : "f"(xi), "f"(cy), "f"(q.x), "f"(q.y), "f"(px));
    }
    #pragma unroll
    for (int o = 16; o; o >>= 1) {
        n      +=              __shfl_xor_sync(FULL, n,      o);
        xallmx = fmaxf(xallmx, __shfl_xor_sync(FULL, xallmx, o));
        xallmn = fminf(xallmn, __shfl_xor_sync(FULL, xallmn, o));
        xs     = fminf(xs,     __shfl_xor_sync(FULL, xs,     o));
        xinf   = fmaxf(xinf,   __shfl_xor_sync(FULL, xinf,   o));
    }

    // condB => xi in [0,1]; presence <=> sentinel moved
    int hs = xs   <  SENTF;
    int hi = xinf > -SENTF;
    int valid = (n == 2) || (n > 2 && hs && hi);
    float dx  = (n == 2) ? (xallmx - xallmn) : (xs - xinf);
    float L2v = fabsf(dx);
    float d1  = fabsf(cy - 1.0f);
    float d2  = fabsf(px - 1.0f);

    // ---- Table min over T=512 rows ----
    float pm = INFF;
    #pragma unroll 4
    for (int t = lane; t < T_N; t += 32) {
        float4 r = __ldg(&g_tbl[t]);
        float al = fabsf(L1v - r.x) + fabsf(L2v - r.y)
                 + fabsf(d1  - r.z) + fabsf(d2  - r.w);
        pm = fminf(pm, al);
    }
    #pragma unroll
    for (int o = 16; o; o >>= 1)
        pm = fminf(pm, __shfl_xor_sync(FULL, pm, o));

    if (lane == 0) {
        g_m[p]     = valid ? pm : BIGF;
        g_valid[p] = valid;
    }
}

// ---------------------------------------------------------------------------
// K3: cummin + masked sum (1 block, 256 threads, shuffle-based scan)
// ---------------------------------------------------------------------------
__global__ void __launch_bounds__(256) scan_kernel(float* __restrict__ out) {
    const unsigned FULL = 0xffffffffu;
    __shared__ float s_wtot[8];
    __shared__ float s_sum[8];
    const int tid  = threadIdx.x;
    const int lane = tid & 31;
    const int wid  = tid >> 5;
    const int base = tid * 16;

    float c[16];
    float run = INFF;
    #pragma unroll
    for (int i = 0; i < 16; i++) {
        run = fminf(run, g_m[base + i]);
        c[i] = run;
    }

    float scan = run;
    #pragma unroll
    for (int o = 1; o < 32; o <<= 1) {
        float v = __shfl_up_sync(FULL, scan, o);
        if (lane >= o) scan = fminf(scan, v);
    }
    if (lane == 31) s_wtot[wid] = scan;
    __syncthreads();

    float wpre = INFF;
    #pragma unroll
    for (int w = 0; w < 8; w++)
        if (w < wid) wpre = fminf(wpre, s_wtot[w]);

    float lpre = __shfl_up_sync(FULL, scan, 1);
    float pre = fminf(wpre, (lane == 0) ? INFF : lpre);

    float acc = 0.0f;
    #pragma unroll
    for (int i = 0; i < 16; i++)
        if (g_valid[base + i]) acc += fminf(pre, c[i]);

    #pragma unroll
    for (int o = 16; o; o >>= 1)
        acc += __shfl_xor_sync(FULL, acc, o);
    if (lane == 0) s_sum[wid] = acc;
    __syncthreads();
    if (tid == 0) {
        float s = 0.0f;
        #pragma unroll
        for (int w = 0; w < 8; w++) s += s_sum[w];
        out[0] = s;
    }
}

// ---------------------------------------------------------------------------
extern "C" void kernel_launch(void* const* d_in, const int* in_sizes, int n_in,
                              void* d_out, int out_size) {
    const float* verts   = (const float*)d_in[0];
    const float* tableR  = (const float*)d_in[1];
    const int*   edges   = (const int*)  d_in[2];
    const int*   listAll = (const int*)  d_in[3];

    prep_kernel <<<64,   64>>>(verts, tableR, edges);
    point_kernel<<<512, 256>>>(verts, listAll);
    scan_kernel <<<1,   256>>>((float*)d_out);
}